// round 1
// baseline (speedup 1.0000x reference)
#include <cuda_runtime.h>

// RNNModel: 2-layer tanh RNN, B=2048, T=512, I=5, H=64, O=1.
// Strategy: batch-parallel, exact fp32 via packed fma.rn.f32x2 (Blackwell FFMA2).
// 1 warp = 2 batch rows; thread ln owns hidden units (ln, ln+32).
// Weights packed in smem so the inner loop is 1 LDS.128(W) + 2 LDS.128(h,broadcast)
// + 4 FFMA2 per 2 k-values per 2 rows. Hidden state double-buffered in per-warp smem.

#define BB 2048
#define TT 512
#define II 5

// shared memory layout (float offsets)
#define OFF_W0   0        // W_hh0 packed float4: [k2][ln] = (W[ln][2k2],W[ln+32][2k2],W[ln][2k2+1],W[ln+32][2k2+1])
#define OFF_W1I  4096     // W_ih1 packed
#define OFF_W1H  8192     // W_hh1 packed
#define OFF_WI0  12288    // W_ih0 packed float2: [i][ln] = (W[ln][i], W[ln+32][i])   (5*64 floats)
#define OFF_B0   12608    // (b_ih0+b_hh0) packed float2 [ln]
#define OFF_B1   12672
#define OFF_FC   12736    // fc_W packed float2 [ln]
#define OFF_H    12800    // per-warp hidden: 4 warps * 1024 floats
#define SMEM_FLOATS (12800 + 4*1024)
#define SMEM_BYTES (SMEM_FLOATS*4)

__device__ __forceinline__ void fma2(unsigned long long &a, unsigned long long b, unsigned long long c){
    asm("fma.rn.f32x2 %0, %1, %2, %0;" : "+l"(a) : "l"(b), "l"(c));
}
__device__ __forceinline__ unsigned long long dup2(float v){
    unsigned long long r; asm("mov.b64 %0, {%1, %1};" : "=l"(r) : "f"(v)); return r;
}
__device__ __forceinline__ void unpk(unsigned long long a, float &lo, float &hi){
    asm("mov.b64 {%0, %1}, %2;" : "=f"(lo), "=f"(hi) : "l"(a));
}
// branch-free tanh: 1 - 2/(exp2(2x*log2e)+1). Saturates correctly at +/-1. err ~1e-6.
__device__ __forceinline__ float fast_tanh(float x){
    float e;
    asm("ex2.approx.f32 %0, %1;" : "=f"(e) : "f"(x * 2.8853900817779268f));
    float r;
    asm("rcp.approx.f32 %0, %1;" : "=f"(r) : "f"(e + 1.0f));
    return fmaf(-2.0f, r, 1.0f);
}

__global__ void __launch_bounds__(128) rnn_f32x2_kernel(
    const float* __restrict__ x,
    const float* __restrict__ W_ih0, const float* __restrict__ W_hh0,
    const float* __restrict__ b_ih0, const float* __restrict__ b_hh0,
    const float* __restrict__ W_ih1, const float* __restrict__ W_hh1,
    const float* __restrict__ b_ih1, const float* __restrict__ b_hh1,
    const float* __restrict__ fc_W,  const float* __restrict__ fc_b,
    float* __restrict__ out)
{
    extern __shared__ float sm[];
    const int tid  = threadIdx.x;
    const int warp = tid >> 5;
    const int ln   = tid & 31;

    // ---- one-time weight packing into smem ----
    for (int idx = tid; idx < 1024; idx += 128){
        int k2 = idx >> 5, l = idx & 31, k = k2 * 2;
        ((float4*)(sm + OFF_W0 ))[idx] = make_float4(W_hh0[l*64+k], W_hh0[(l+32)*64+k], W_hh0[l*64+k+1], W_hh0[(l+32)*64+k+1]);
        ((float4*)(sm + OFF_W1I))[idx] = make_float4(W_ih1[l*64+k], W_ih1[(l+32)*64+k], W_ih1[l*64+k+1], W_ih1[(l+32)*64+k+1]);
        ((float4*)(sm + OFF_W1H))[idx] = make_float4(W_hh1[l*64+k], W_hh1[(l+32)*64+k], W_hh1[l*64+k+1], W_hh1[(l+32)*64+k+1]);
    }
    for (int idx = tid; idx < 5*32; idx += 128){
        int i = idx >> 5, l = idx & 31;
        ((float2*)(sm + OFF_WI0))[idx] = make_float2(W_ih0[l*5+i], W_ih0[(l+32)*5+i]);
    }
    if (tid < 32){
        ((float2*)(sm + OFF_B0))[tid] = make_float2(b_ih0[tid]+b_hh0[tid], b_ih0[tid+32]+b_hh0[tid+32]);
        ((float2*)(sm + OFF_B1))[tid] = make_float2(b_ih1[tid]+b_hh1[tid], b_ih1[tid+32]+b_hh1[tid+32]);
        ((float2*)(sm + OFF_FC))[tid] = make_float2(fc_W[tid], fc_W[tid+32]);
    }
    for (int idx = tid; idx < 4*1024; idx += 128) sm[OFF_H + idx] = 0.0f;
    __syncthreads();

    const int r0 = blockIdx.x * 8 + warp * 2;   // this warp's 2 batch rows

    // per-warp hidden area: h1 at [0,512), h2 at [512,1024); each: [buf][row][128 floats, k duplicated]
    float* hw = sm + OFF_H + warp * 1024;

    const unsigned long long b0u = *(const unsigned long long*)(sm + OFF_B0 + 2*ln);
    const unsigned long long b1u = *(const unsigned long long*)(sm + OFF_B1 + 2*ln);

    // x prefetch: lanes 0..9 stream (row, i) pairs
    const int li = (ln < 10) ? ln : 0;
    const float* xp = x + (size_t)(r0 + (li / 5)) * (TT * II) + (li % 5);
    float xv = xp[0];

    const ulonglong2* W0  = (const ulonglong2*)(sm + OFF_W0);
    const ulonglong2* W1I = (const ulonglong2*)(sm + OFF_W1I);
    const ulonglong2* W1H = (const ulonglong2*)(sm + OFF_W1H);

    float t20 = 0.f, t21 = 0.f, t30 = 0.f, t31 = 0.f;  // final layer-2 h for fc
    int p = 0;

    for (int t = 0; t < TT; t++){
        float xc = xv;
        if (t + 1 < TT) xv = xp[(t + 1) * II];

        // ---------- layer 1: a = b0 + x_t @ Wih0^T + h1 @ Whh0^T ----------
        unsigned long long a0 = b0u, a1 = b0u;
        #pragma unroll
        for (int i = 0; i < 5; i++){
            float x0 = __shfl_sync(0xffffffffu, xc, i);
            float x1 = __shfl_sync(0xffffffffu, xc, 5 + i);
            unsigned long long w = *(const unsigned long long*)(sm + OFF_WI0 + (i*32 + ln)*2);
            fma2(a0, w, dup2(x0));
            fma2(a1, w, dup2(x1));
        }
        {
            const ulonglong2* h0 = (const ulonglong2*)(hw + p*256);
            const ulonglong2* h1 = (const ulonglong2*)(hw + p*256 + 128);
            #pragma unroll
            for (int k2 = 0; k2 < 32; k2++){
                ulonglong2 w  = W0[k2*32 + ln];
                ulonglong2 hA = h0[k2];
                ulonglong2 hB = h1[k2];
                fma2(a0, w.x, hA.x); fma2(a0, w.y, hA.y);
                fma2(a1, w.x, hB.x); fma2(a1, w.y, hB.y);
            }
        }
        const int q = 1 - p;
        {
            float f00, f01, f10, f11;
            unpk(a0, f00, f01); unpk(a1, f10, f11);
            float u00 = fast_tanh(f00), u01 = fast_tanh(f01);
            float u10 = fast_tanh(f10), u11 = fast_tanh(f11);
            float* d0 = hw + q*256;
            float* d1 = d0 + 128;
            *(float2*)(d0 + 2*ln)        = make_float2(u00, u00);
            *(float2*)(d0 + 2*(ln + 32)) = make_float2(u01, u01);
            *(float2*)(d1 + 2*ln)        = make_float2(u10, u10);
            *(float2*)(d1 + 2*(ln + 32)) = make_float2(u11, u11);
        }
        __syncwarp();

        // ---------- layer 2: a = b1 + h1_new @ Wih1^T + h2 @ Whh1^T ----------
        a0 = b1u; a1 = b1u;
        {
            const ulonglong2* h0 = (const ulonglong2*)(hw + q*256);
            const ulonglong2* h1 = (const ulonglong2*)(hw + q*256 + 128);
            #pragma unroll
            for (int k2 = 0; k2 < 32; k2++){
                ulonglong2 w  = W1I[k2*32 + ln];
                ulonglong2 hA = h0[k2];
                ulonglong2 hB = h1[k2];
                fma2(a0, w.x, hA.x); fma2(a0, w.y, hA.y);
                fma2(a1, w.x, hB.x); fma2(a1, w.y, hB.y);
            }
        }
        {
            const ulonglong2* g0 = (const ulonglong2*)(hw + 512 + p*256);
            const ulonglong2* g1 = (const ulonglong2*)(hw + 512 + p*256 + 128);
            #pragma unroll
            for (int k2 = 0; k2 < 32; k2++){
                ulonglong2 w  = W1H[k2*32 + ln];
                ulonglong2 hA = g0[k2];
                ulonglong2 hB = g1[k2];
                fma2(a0, w.x, hA.x); fma2(a0, w.y, hA.y);
                fma2(a1, w.x, hB.x); fma2(a1, w.y, hB.y);
            }
        }
        {
            float f00, f01, f10, f11;
            unpk(a0, f00, f01); unpk(a1, f10, f11);
            t20 = fast_tanh(f00); t21 = fast_tanh(f01);
            t30 = fast_tanh(f10); t31 = fast_tanh(f11);
            float* d0 = hw + 512 + q*256;
            float* d1 = d0 + 128;
            *(float2*)(d0 + 2*ln)        = make_float2(t20, t20);
            *(float2*)(d0 + 2*(ln + 32)) = make_float2(t21, t21);
            *(float2*)(d1 + 2*ln)        = make_float2(t30, t30);
            *(float2*)(d1 + 2*(ln + 32)) = make_float2(t31, t31);
        }
        __syncwarp();
        p = q;
    }

    // ---------- fc: out[b] = h2 . fc_W + fc_b ----------
    float2 fw = *(const float2*)(sm + OFF_FC + 2*ln);
    float p0 = t20 * fw.x + t21 * fw.y;
    float p1 = t30 * fw.x + t31 * fw.y;
    #pragma unroll
    for (int o = 16; o; o >>= 1){
        p0 += __shfl_xor_sync(0xffffffffu, p0, o);
        p1 += __shfl_xor_sync(0xffffffffu, p1, o);
    }
    if (ln == 0){
        float fb = fc_b[0];
        out[r0]     = p0 + fb;
        out[r0 + 1] = p1 + fb;
    }
}

extern "C" void kernel_launch(void* const* d_in, const int* in_sizes, int n_in,
                              void* d_out, int out_size)
{
    const float* x     = (const float*)d_in[0];
    const float* W_ih0 = (const float*)d_in[1];
    const float* W_hh0 = (const float*)d_in[2];
    const float* b_ih0 = (const float*)d_in[3];
    const float* b_hh0 = (const float*)d_in[4];
    const float* W_ih1 = (const float*)d_in[5];
    const float* W_hh1 = (const float*)d_in[6];
    const float* b_ih1 = (const float*)d_in[7];
    const float* b_hh1 = (const float*)d_in[8];
    const float* fc_W  = (const float*)d_in[9];
    const float* fc_b  = (const float*)d_in[10];
    float* out = (float*)d_out;

    // >48KB dynamic smem (67.5KB): attribute set is sticky; first call happens
    // outside graph capture. Ignore return value (idempotent thereafter).
    cudaFuncSetAttribute(rnn_f32x2_kernel,
                         cudaFuncAttributeMaxDynamicSharedMemorySize, SMEM_BYTES);

    rnn_f32x2_kernel<<<BB / 8, 128, SMEM_BYTES>>>(
        x, W_ih0, W_hh0, b_ih0, b_hh0, W_ih1, W_hh1, b_ih1, b_hh1, fc_W, fc_b, out);
}

// round 2
// speedup vs baseline: 1.8844x; 1.8844x over previous
#include <cuda_runtime.h>

// RNNModel: 2-layer tanh RNN, B=2048, T=512, I=5, H=64, O=1.
// R2: crossbar-bound fix.
//  - 4 batch rows per warp: each lane-distinct W LDS.128 feeds 8 FFMA2.
//  - f32x2 packed over k (acc = even-k/odd-k partials, horizontal add at end):
//    h multiplier is the natural (h_k, h_{k+1}) pair -> no duplicated h storage,
//    1 broadcast LDS.128 of h covers 4 k-values per row.
//  - W_ih0 (5 cols) kept in registers; x broadcast via shfl.
// Grid: 128 CTAs x 128 thr (4 warps, 16 rows/CTA); 1 warp per SMSP.

#define BB 2048
#define TT 512
#define II 5

// shared float offsets
#define OFF_W0   0        // W_hh0: [k2][ln] float4 = (W[ln][2k2], W[ln][2k2+1], W[ln+32][2k2], W[ln+32][2k2+1])
#define OFF_W1I  4096     // W_ih1 same packing
#define OFF_W1H  8192     // W_hh1 same packing
#define OFF_H    12288    // per-warp hidden: 4 warps * 512 floats (h1[4][64], h2[4][64])
#define SMEM_FLOATS (12288 + 4*512)
#define SMEM_BYTES (SMEM_FLOATS*4)

typedef unsigned long long ull;

__device__ __forceinline__ void fma2(ull &a, ull b, ull c){
    asm("fma.rn.f32x2 %0, %1, %2, %0;" : "+l"(a) : "l"(b), "l"(c));
}
__device__ __forceinline__ ull pack2(float lo, float hi){
    ull r; asm("mov.b64 %0, {%1, %2};" : "=l"(r) : "f"(lo), "f"(hi)); return r;
}
__device__ __forceinline__ void unpk(ull a, float &lo, float &hi){
    asm("mov.b64 {%0, %1}, %2;" : "=f"(lo), "=f"(hi) : "l"(a));
}
// branch-free tanh: 1 - 2/(exp2(2x*log2e)+1). err ~1e-6, correct +/-1 saturation.
__device__ __forceinline__ float fast_tanh(float x){
    float e;
    asm("ex2.approx.f32 %0, %1;" : "=f"(e) : "f"(x * 2.8853900817779268f));
    float r;
    asm("rcp.approx.f32 %0, %1;" : "=f"(r) : "f"(e + 1.0f));
    return fmaf(-2.0f, r, 1.0f);
}

__global__ void __launch_bounds__(128, 1) rnn_r4_kernel(
    const float* __restrict__ x,
    const float* __restrict__ W_ih0, const float* __restrict__ W_hh0,
    const float* __restrict__ b_ih0, const float* __restrict__ b_hh0,
    const float* __restrict__ W_ih1, const float* __restrict__ W_hh1,
    const float* __restrict__ b_ih1, const float* __restrict__ b_hh1,
    const float* __restrict__ fc_W,  const float* __restrict__ fc_b,
    float* __restrict__ out)
{
    extern __shared__ float sm[];
    const int tid  = threadIdx.x;
    const int warp = tid >> 5;
    const int ln   = tid & 31;

    // ---- one-time weight packing: [k2][ln] float4 = (W[l][2k2], W[l][2k2+1], W[l+32][2k2], W[l+32][2k2+1])
    for (int idx = tid; idx < 1024; idx += 128){
        int k2 = idx >> 5, l = idx & 31, k = k2 * 2;
        ((float4*)(sm + OFF_W0 ))[idx] = make_float4(W_hh0[l*64+k], W_hh0[l*64+k+1], W_hh0[(l+32)*64+k], W_hh0[(l+32)*64+k+1]);
        ((float4*)(sm + OFF_W1I))[idx] = make_float4(W_ih1[l*64+k], W_ih1[l*64+k+1], W_ih1[(l+32)*64+k], W_ih1[(l+32)*64+k+1]);
        ((float4*)(sm + OFF_W1H))[idx] = make_float4(W_hh1[l*64+k], W_hh1[l*64+k+1], W_hh1[(l+32)*64+k], W_hh1[(l+32)*64+k+1]);
    }
    // zero hidden state
    for (int idx = tid; idx < 4*512; idx += 128) sm[OFF_H + idx] = 0.0f;
    __syncthreads();

    const int r0 = blockIdx.x * 16 + warp * 4;      // this warp's 4 batch rows
    float* h1 = sm + OFF_H + warp * 512;            // h1[4][64]
    float* h2 = h1 + 256;                           // h2[4][64]

    // per-lane constants (registers)
    float wi0a[5], wi0b[5];
    #pragma unroll
    for (int i = 0; i < 5; i++){
        wi0a[i] = W_ih0[ln*5 + i];
        wi0b[i] = W_ih0[(ln+32)*5 + i];
    }
    const float b0a = b_ih0[ln]      + b_hh0[ln];
    const float b0b = b_ih0[ln+32]   + b_hh0[ln+32];
    const float b1a = b_ih1[ln]      + b_hh1[ln];
    const float b1b = b_ih1[ln+32]   + b_hh1[ln+32];

    // x prefetch: lanes 0..19 stream (row, i); row = ln/5, i = ln%5
    const int li = (ln < 20) ? ln : 0;
    const float* xp = x + (size_t)(r0 + li/5) * (TT*II) + (li % 5);
    float xv = xp[0];

    const ulonglong2* W0p  = (const ulonglong2*)(sm + OFF_W0)  + ln;
    const ulonglong2* W1Ip = (const ulonglong2*)(sm + OFF_W1I) + ln;
    const ulonglong2* W1Hp = (const ulonglong2*)(sm + OFF_W1H) + ln;

    float ta[4], tb[4];   // last layer-2 outputs per row
    #pragma unroll
    for (int r = 0; r < 4; r++){ ta[r] = 0.f; tb[r] = 0.f; }

    for (int t = 0; t < TT; t++){
        float xc = xv;
        if (t + 1 < TT) xv = xp[(t + 1) * II];

        // ================= layer 1 =================
        ull aA[4], aB[4];
        #pragma unroll
        for (int r = 0; r < 4; r++){
            float sa = b0a, sb = b0b;
            #pragma unroll
            for (int i = 0; i < 5; i++){
                float xr = __shfl_sync(0xffffffffu, xc, r*5 + i);
                sa = fmaf(xr, wi0a[i], sa);
                sb = fmaf(xr, wi0b[i], sb);
            }
            aA[r] = pack2(sa, 0.0f);
            aB[r] = pack2(sb, 0.0f);
        }
        // h1_old @ W_hh0^T
        #pragma unroll
        for (int kk = 0; kk < 16; kk++){            // 4 k per iter
            ulonglong2 w0 = W0p[(2*kk  )*32];       // k-pair 2kk   : (a-pair, b-pair)
            ulonglong2 w1 = W0p[(2*kk+1)*32];       // k-pair 2kk+1
            #pragma unroll
            for (int r = 0; r < 4; r++){
                ulonglong2 hq = *(const ulonglong2*)(h1 + r*64 + kk*4);  // broadcast
                fma2(aA[r], w0.x, hq.x); fma2(aB[r], w0.y, hq.x);
                fma2(aA[r], w1.x, hq.y); fma2(aB[r], w1.y, hq.y);
            }
        }
        __syncwarp();   // all lanes done reading h1_old
        #pragma unroll
        for (int r = 0; r < 4; r++){
            float lo, hi;
            unpk(aA[r], lo, hi); float u1a = fast_tanh(lo + hi);
            unpk(aB[r], lo, hi); float u1b = fast_tanh(lo + hi);
            h1[r*64 + ln]      = u1a;
            h1[r*64 + ln + 32] = u1b;
        }
        __syncwarp();   // h1_new visible

        // ================= layer 2 =================
        #pragma unroll
        for (int r = 0; r < 4; r++){
            aA[r] = pack2(b1a, 0.0f);
            aB[r] = pack2(b1b, 0.0f);
        }
        // h1_new @ W_ih1^T
        #pragma unroll
        for (int kk = 0; kk < 16; kk++){
            ulonglong2 w0 = W1Ip[(2*kk  )*32];
            ulonglong2 w1 = W1Ip[(2*kk+1)*32];
            #pragma unroll
            for (int r = 0; r < 4; r++){
                ulonglong2 hq = *(const ulonglong2*)(h1 + r*64 + kk*4);
                fma2(aA[r], w0.x, hq.x); fma2(aB[r], w0.y, hq.x);
                fma2(aA[r], w1.x, hq.y); fma2(aB[r], w1.y, hq.y);
            }
        }
        // h2_old @ W_hh1^T
        #pragma unroll
        for (int kk = 0; kk < 16; kk++){
            ulonglong2 w0 = W1Hp[(2*kk  )*32];
            ulonglong2 w1 = W1Hp[(2*kk+1)*32];
            #pragma unroll
            for (int r = 0; r < 4; r++){
                ulonglong2 gq = *(const ulonglong2*)(h2 + r*64 + kk*4);
                fma2(aA[r], w0.x, gq.x); fma2(aB[r], w0.y, gq.x);
                fma2(aA[r], w1.x, gq.y); fma2(aB[r], w1.y, gq.y);
            }
        }
        __syncwarp();   // all lanes done reading h2_old
        #pragma unroll
        for (int r = 0; r < 4; r++){
            float lo, hi;
            unpk(aA[r], lo, hi); ta[r] = fast_tanh(lo + hi);
            unpk(aB[r], lo, hi); tb[r] = fast_tanh(lo + hi);
            h2[r*64 + ln]      = ta[r];
            h2[r*64 + ln + 32] = tb[r];
        }
        __syncwarp();   // h2_new visible for next step
    }

    // ================= fc =================
    const float fa = fc_W[ln], fb = fc_W[ln+32];
    #pragma unroll
    for (int r = 0; r < 4; r++){
        float p = ta[r]*fa + tb[r]*fb;
        #pragma unroll
        for (int o = 16; o; o >>= 1)
            p += __shfl_xor_sync(0xffffffffu, p, o);
        if (ln == 0) out[r0 + r] = p + fc_b[0];
    }
}

extern "C" void kernel_launch(void* const* d_in, const int* in_sizes, int n_in,
                              void* d_out, int out_size)
{
    const float* x     = (const float*)d_in[0];
    const float* W_ih0 = (const float*)d_in[1];
    const float* W_hh0 = (const float*)d_in[2];
    const float* b_ih0 = (const float*)d_in[3];
    const float* b_hh0 = (const float*)d_in[4];
    const float* W_ih1 = (const float*)d_in[5];
    const float* W_hh1 = (const float*)d_in[6];
    const float* b_ih1 = (const float*)d_in[7];
    const float* b_hh1 = (const float*)d_in[8];
    const float* fc_W  = (const float*)d_in[9];
    const float* fc_b  = (const float*)d_in[10];
    float* out = (float*)d_out;

    cudaFuncSetAttribute(rnn_r4_kernel,
                         cudaFuncAttributeMaxDynamicSharedMemorySize, SMEM_BYTES);

    rnn_r4_kernel<<<BB / 16, 128, SMEM_BYTES>>>(
        x, W_ih0, W_hh0, b_ih0, b_hh0, W_ih1, W_hh1, b_ih1, b_hh1, fc_W, fc_b, out);
}

// round 3
// speedup vs baseline: 1.9464x; 1.0329x over previous
#include <cuda_runtime.h>

// RNNModel: 2-layer tanh RNN, B=2048, T=512, I=5, H=64, O=1.
// R3: latency-gap closure. Crossbar floor is 2368 cyc/SM/step; measured 3200.
//  - cross-barrier prefetch (W/stable-h loads hoisted above __syncwarp)
//  - depth-1 register pipelining in both matvec loops
//  - x via smem chunk staging (no shfl chain)
//  - fused layer-2 loop (12 loads + 32 FFMA2 per iter)

#define BB 2048
#define TT 512
#define II 5

#define OFF_W0   0        // W_hh0 [k2][ln] float4 = (W[l][2k2],W[l][2k2+1],W[l+32][2k2],W[l+32][2k2+1])
#define OFF_W1I  4096
#define OFF_W1H  8192
#define OFF_X    12288    // per-warp x stage: 4 warps * 512 floats ([r][tc][8] padded)
#define OFF_H    14336    // per-warp hidden: 4 warps * 512 (h1[4][64], h2[4][64])
#define SMEM_FLOATS (14336 + 2048)
#define SMEM_BYTES (SMEM_FLOATS*4)

typedef unsigned long long ull;

__device__ __forceinline__ void fma2(ull &a, ull b, ull c){
    asm("fma.rn.f32x2 %0, %1, %2, %0;" : "+l"(a) : "l"(b), "l"(c));
}
__device__ __forceinline__ ull pack2(float lo, float hi){
    ull r; asm("mov.b64 %0, {%1, %2};" : "=l"(r) : "f"(lo), "f"(hi)); return r;
}
__device__ __forceinline__ void unpk(ull a, float &lo, float &hi){
    asm("mov.b64 {%0, %1}, %2;" : "=f"(lo), "=f"(hi) : "l"(a));
}
__device__ __forceinline__ float fast_tanh(float x){
    float e;
    asm("ex2.approx.f32 %0, %1;" : "=f"(e) : "f"(x * 2.8853900817779268f));
    float r;
    asm("rcp.approx.f32 %0, %1;" : "=f"(r) : "f"(e + 1.0f));
    return fmaf(-2.0f, r, 1.0f);
}

// x chunk staging: 16 steps * 4 rows * 5 floats = 320 elements, 10 per lane.
__device__ __forceinline__ void ld_chunk(const float* __restrict__ x, float* xg,
                                         int r0, int ln, int c){
    #pragma unroll
    for (int s = 0; s < 10; s++){
        int e = ln + 32*s;
        int r = e / 80, rem = e % 80;
        xg[s] = x[(size_t)(r0 + r) * (TT*II) + (size_t)c * 80 + rem];
    }
}
__device__ __forceinline__ void st_chunk(float* xw, const float* xg, int ln){
    #pragma unroll
    for (int s = 0; s < 10; s++){
        int e = ln + 32*s;
        int r = e / 80, rem = e % 80;
        int tc = rem / 5, i = rem - tc*5;
        xw[r*128 + tc*8 + i] = xg[s];
    }
}

__global__ void __launch_bounds__(128, 1) rnn_r5_kernel(
    const float* __restrict__ x,
    const float* __restrict__ W_ih0, const float* __restrict__ W_hh0,
    const float* __restrict__ b_ih0, const float* __restrict__ b_hh0,
    const float* __restrict__ W_ih1, const float* __restrict__ W_hh1,
    const float* __restrict__ b_ih1, const float* __restrict__ b_hh1,
    const float* __restrict__ fc_W,  const float* __restrict__ fc_b,
    float* __restrict__ out)
{
    extern __shared__ float sm[];
    const int tid  = threadIdx.x;
    const int warp = tid >> 5;
    const int ln   = tid & 31;

    // ---- one-time weight packing ----
    for (int idx = tid; idx < 1024; idx += 128){
        int k2 = idx >> 5, l = idx & 31, k = k2 * 2;
        ((float4*)(sm + OFF_W0 ))[idx] = make_float4(W_hh0[l*64+k], W_hh0[l*64+k+1], W_hh0[(l+32)*64+k], W_hh0[(l+32)*64+k+1]);
        ((float4*)(sm + OFF_W1I))[idx] = make_float4(W_ih1[l*64+k], W_ih1[l*64+k+1], W_ih1[(l+32)*64+k], W_ih1[(l+32)*64+k+1]);
        ((float4*)(sm + OFF_W1H))[idx] = make_float4(W_hh1[l*64+k], W_hh1[l*64+k+1], W_hh1[(l+32)*64+k], W_hh1[(l+32)*64+k+1]);
    }
    for (int idx = tid; idx < 4*512; idx += 128) sm[OFF_H + idx] = 0.0f;
    __syncthreads();

    const int r0 = blockIdx.x * 16 + warp * 4;
    float* h1 = sm + OFF_H + warp * 512;   // h1[4][64]
    float* h2 = h1 + 256;                  // h2[4][64]
    float* xw = sm + OFF_X + warp * 512;   // x stage [4][16][8]

    float wa[5], wb[5];
    #pragma unroll
    for (int i = 0; i < 5; i++){
        wa[i] = W_ih0[ln*5 + i];
        wb[i] = W_ih0[(ln+32)*5 + i];
    }
    const float b0a = b_ih0[ln]    + b_hh0[ln];
    const float b0b = b_ih0[ln+32] + b_hh0[ln+32];
    const float b1a = b_ih1[ln]    + b_hh1[ln];
    const float b1b = b_ih1[ln+32] + b_hh1[ln+32];

    const ulonglong2* W0p  = (const ulonglong2*)(sm + OFF_W0)  + ln;
    const ulonglong2* W1Ip = (const ulonglong2*)(sm + OFF_W1I) + ln;
    const ulonglong2* W1Hp = (const ulonglong2*)(sm + OFF_W1H) + ln;

    // x chunk 0 -> smem; start chunk 1 in flight
    float xg[10];
    ld_chunk(x, xg, r0, ln, 0);
    st_chunk(xw, xg, ln);
    __syncwarp();
    ld_chunk(x, xg, r0, ln, 1);

    // steady-state preloads for layer-1 kk=0
    ulonglong2 pw0 = W0p[0], pw1 = W0p[32];
    ulonglong2 ph0 = *(const ulonglong2*)(h1 +   0);
    ulonglong2 ph1 = *(const ulonglong2*)(h1 +  64);
    ulonglong2 ph2 = *(const ulonglong2*)(h1 + 128);
    ulonglong2 ph3 = *(const ulonglong2*)(h1 + 192);

    float ta[4], tb[4];
    #pragma unroll
    for (int r = 0; r < 4; r++){ ta[r] = 0.f; tb[r] = 0.f; }

    for (int t = 0; t < TT; t++){
        const int tc = t & 15;
        if (tc == 0 && t){
            st_chunk(xw, xg, ln);
            __syncwarp();
            int c = (t >> 4) + 1;
            if (c < 32) ld_chunk(x, xg, r0, ln, c);
        }

        // ---- layer 1 init: bias + x projection (from smem stage) ----
        ull aA[4], aB[4];
        #pragma unroll
        for (int r = 0; r < 4; r++){
            const float* xr = xw + r*128 + tc*8;
            float4 xv = *(const float4*)xr;
            float x4  = xr[4];
            float sa = b0a, sb = b0b;
            sa = fmaf(xv.x, wa[0], sa); sb = fmaf(xv.x, wb[0], sb);
            sa = fmaf(xv.y, wa[1], sa); sb = fmaf(xv.y, wb[1], sb);
            sa = fmaf(xv.z, wa[2], sa); sb = fmaf(xv.z, wb[2], sb);
            sa = fmaf(xv.w, wa[3], sa); sb = fmaf(xv.w, wb[3], sb);
            sa = fmaf(x4,   wa[4], sa); sb = fmaf(x4,   wb[4], sb);
            aA[r] = pack2(sa, 0.f); aB[r] = pack2(sb, 0.f);
        }

        // ---- layer 1: h1_old @ W_hh0^T (pipelined, preloaded kk=0) ----
        {
            ulonglong2 cw0 = pw0, cw1 = pw1;
            ulonglong2 c0 = ph0, c1 = ph1, c2 = ph2, c3 = ph3;
            #pragma unroll
            for (int kk = 0; kk < 16; kk++){
                const int kn = (kk < 15) ? kk + 1 : 15;
                ulonglong2 nw0 = W0p[(2*kn  )*32];
                ulonglong2 nw1 = W0p[(2*kn+1)*32];
                ulonglong2 n0 = *(const ulonglong2*)(h1 +   0 + kn*4);
                ulonglong2 n1 = *(const ulonglong2*)(h1 +  64 + kn*4);
                ulonglong2 n2 = *(const ulonglong2*)(h1 + 128 + kn*4);
                ulonglong2 n3 = *(const ulonglong2*)(h1 + 192 + kn*4);
                fma2(aA[0],cw0.x,c0.x); fma2(aB[0],cw0.y,c0.x); fma2(aA[0],cw1.x,c0.y); fma2(aB[0],cw1.y,c0.y);
                fma2(aA[1],cw0.x,c1.x); fma2(aB[1],cw0.y,c1.x); fma2(aA[1],cw1.x,c1.y); fma2(aB[1],cw1.y,c1.y);
                fma2(aA[2],cw0.x,c2.x); fma2(aB[2],cw0.y,c2.x); fma2(aA[2],cw1.x,c2.y); fma2(aB[2],cw1.y,c2.y);
                fma2(aA[3],cw0.x,c3.x); fma2(aB[3],cw0.y,c3.x); fma2(aA[3],cw1.x,c3.y); fma2(aB[3],cw1.y,c3.y);
                cw0 = nw0; cw1 = nw1; c0 = n0; c1 = n1; c2 = n2; c3 = n3;
            }
        }

        // prefetch layer-2 kk=0 operands (W const, h2 stable) BEFORE the barrier
        ulonglong2 qI0 = W1Ip[0], qI1 = W1Ip[32];
        ulonglong2 qH0 = W1Hp[0], qH1 = W1Hp[32];
        ulonglong2 qg0 = *(const ulonglong2*)(h2 +   0);
        ulonglong2 qg1 = *(const ulonglong2*)(h2 +  64);
        ulonglong2 qg2 = *(const ulonglong2*)(h2 + 128);
        ulonglong2 qg3 = *(const ulonglong2*)(h2 + 192);

        float u0[4], u1[4];
        #pragma unroll
        for (int r = 0; r < 4; r++){
            float lo, hi;
            unpk(aA[r], lo, hi); u0[r] = fast_tanh(lo + hi);
            unpk(aB[r], lo, hi); u1[r] = fast_tanh(lo + hi);
        }
        __syncwarp();                       // all lanes finished reading h1_old
        #pragma unroll
        for (int r = 0; r < 4; r++){
            h1[r*64 + ln]      = u0[r];
            h1[r*64 + ln + 32] = u1[r];
        }
        __syncwarp();                       // h1_new visible

        // ---- layer 2: fused h1_new @ W_ih1^T + h2_old @ W_hh1^T ----
        #pragma unroll
        for (int r = 0; r < 4; r++){ aA[r] = pack2(b1a, 0.f); aB[r] = pack2(b1b, 0.f); }
        {
            ulonglong2 cI0 = qI0, cI1 = qI1, cH0 = qH0, cH1 = qH1;
            ulonglong2 g0 = qg0, g1 = qg1, g2 = qg2, g3 = qg3;
            ulonglong2 e0 = *(const ulonglong2*)(h1 +   0);
            ulonglong2 e1 = *(const ulonglong2*)(h1 +  64);
            ulonglong2 e2 = *(const ulonglong2*)(h1 + 128);
            ulonglong2 e3 = *(const ulonglong2*)(h1 + 192);
            #pragma unroll
            for (int kk = 0; kk < 16; kk++){
                const int kn = (kk < 15) ? kk + 1 : 15;
                ulonglong2 nI0 = W1Ip[(2*kn  )*32];
                ulonglong2 nI1 = W1Ip[(2*kn+1)*32];
                ulonglong2 nH0 = W1Hp[(2*kn  )*32];
                ulonglong2 nH1 = W1Hp[(2*kn+1)*32];
                ulonglong2 m0 = *(const ulonglong2*)(h1 +   0 + kn*4);
                ulonglong2 m1 = *(const ulonglong2*)(h1 +  64 + kn*4);
                ulonglong2 m2 = *(const ulonglong2*)(h1 + 128 + kn*4);
                ulonglong2 m3 = *(const ulonglong2*)(h1 + 192 + kn*4);
                ulonglong2 o0 = *(const ulonglong2*)(h2 +   0 + kn*4);
                ulonglong2 o1 = *(const ulonglong2*)(h2 +  64 + kn*4);
                ulonglong2 o2 = *(const ulonglong2*)(h2 + 128 + kn*4);
                ulonglong2 o3 = *(const ulonglong2*)(h2 + 192 + kn*4);
                // h2-side (operands preloaded longest)
                fma2(aA[0],cH0.x,g0.x); fma2(aB[0],cH0.y,g0.x); fma2(aA[0],cH1.x,g0.y); fma2(aB[0],cH1.y,g0.y);
                fma2(aA[1],cH0.x,g1.x); fma2(aB[1],cH0.y,g1.x); fma2(aA[1],cH1.x,g1.y); fma2(aB[1],cH1.y,g1.y);
                fma2(aA[2],cH0.x,g2.x); fma2(aB[2],cH0.y,g2.x); fma2(aA[2],cH1.x,g2.y); fma2(aB[2],cH1.y,g2.y);
                fma2(aA[3],cH0.x,g3.x); fma2(aB[3],cH0.y,g3.x); fma2(aA[3],cH1.x,g3.y); fma2(aB[3],cH1.y,g3.y);
                // h1-side
                fma2(aA[0],cI0.x,e0.x); fma2(aB[0],cI0.y,e0.x); fma2(aA[0],cI1.x,e0.y); fma2(aB[0],cI1.y,e0.y);
                fma2(aA[1],cI0.x,e1.x); fma2(aB[1],cI0.y,e1.x); fma2(aA[1],cI1.x,e1.y); fma2(aB[1],cI1.y,e1.y);
                fma2(aA[2],cI0.x,e2.x); fma2(aB[2],cI0.y,e2.x); fma2(aA[2],cI1.x,e2.y); fma2(aB[2],cI1.y,e2.y);
                fma2(aA[3],cI0.x,e3.x); fma2(aB[3],cI0.y,e3.x); fma2(aA[3],cI1.x,e3.y); fma2(aB[3],cI1.y,e3.y);
                cI0=nI0; cI1=nI1; cH0=nH0; cH1=nH1;
                g0=o0; g1=o1; g2=o2; g3=o3;
                e0=m0; e1=m1; e2=m2; e3=m3;
            }
        }
        #pragma unroll
        for (int r = 0; r < 4; r++){
            float lo, hi;
            unpk(aA[r], lo, hi); ta[r] = fast_tanh(lo + hi);
            unpk(aB[r], lo, hi); tb[r] = fast_tanh(lo + hi);
        }
        __syncwarp();                       // all lanes finished reading h2_old
        #pragma unroll
        for (int r = 0; r < 4; r++){
            h2[r*64 + ln]      = ta[r];
            h2[r*64 + ln + 32] = tb[r];
        }
        __syncwarp();                       // h2_new visible

        // prefetch next step's layer-1 kk=0 (W const; h1 stable until next layer-1 write)
        pw0 = W0p[0]; pw1 = W0p[32];
        ph0 = *(const ulonglong2*)(h1 +   0);
        ph1 = *(const ulonglong2*)(h1 +  64);
        ph2 = *(const ulonglong2*)(h1 + 128);
        ph3 = *(const ulonglong2*)(h1 + 192);
    }

    // ---- fc ----
    const float fa = fc_W[ln], fb = fc_W[ln+32];
    #pragma unroll
    for (int r = 0; r < 4; r++){
        float p = ta[r]*fa + tb[r]*fb;
        #pragma unroll
        for (int o = 16; o; o >>= 1)
            p += __shfl_xor_sync(0xffffffffu, p, o);
        if (ln == 0) out[r0 + r] = p + fc_b[0];
    }
}

extern "C" void kernel_launch(void* const* d_in, const int* in_sizes, int n_in,
                              void* d_out, int out_size)
{
    const float* x     = (const float*)d_in[0];
    const float* W_ih0 = (const float*)d_in[1];
    const float* W_hh0 = (const float*)d_in[2];
    const float* b_ih0 = (const float*)d_in[3];
    const float* b_hh0 = (const float*)d_in[4];
    const float* W_ih1 = (const float*)d_in[5];
    const float* W_hh1 = (const float*)d_in[6];
    const float* b_ih1 = (const float*)d_in[7];
    const float* b_hh1 = (const float*)d_in[8];
    const float* fc_W  = (const float*)d_in[9];
    const float* fc_b  = (const float*)d_in[10];
    float* out = (float*)d_out;

    cudaFuncSetAttribute(rnn_r5_kernel,
                         cudaFuncAttributeMaxDynamicSharedMemorySize, SMEM_BYTES);

    rnn_r5_kernel<<<BB / 16, 128, SMEM_BYTES>>>(
        x, W_ih0, W_hh0, b_ih0, b_hh0, W_ih1, W_hh1, b_ih1, b_hh1, fc_W, fc_b, out);
}